// round 13
// baseline (speedup 1.0000x reference)
#include <cuda_runtime.h>
#include <cstdint>

#define NN   50000
#define NE   800000
#define DIN  96
#define DH   128
#define DOUT 16
#define RB   64          // rows per fused block
#define EPB1 128         // edges per block, layer-1 agg

typedef unsigned long long ull;

// ---------------- scratch ----------------
// g_agg1: zeroed at END of each launch (overlapped); statically zero for call 0.
__device__ __align__(16) float g_agg1[NN * DIN];
// g_small: [deg | agg2], zeroed at start (3.4 MB, ~1 us)
#define OFF_DEG  0
#define OFF_AGG2 NN
#define SMALL_TOTAL (NN + NN * DOUT)
__device__ __align__(16) float g_small[SMALL_TOTAL];
__device__ __align__(16) float g_r[NN * 32];       // [p | q] = h @ [W2_l | W2_r]
__device__ __align__(16) ull   g_W1lD[DIN * DH];   // duplicated (w,w) weights
__device__ __align__(16) ull   g_W1rD[DIN * DH];
__device__ int g_is64;

// ---------------- f32x2 packed helpers (sm_100+) ----------------
__device__ __forceinline__ ull pk(float a, float b) {
    ull r; asm("mov.b64 %0, {%1,%2};" : "=l"(r) : "f"(a), "f"(b)); return r;
}
__device__ __forceinline__ float2 upk(ull a) {
    float2 f; asm("mov.b64 {%0,%1}, %2;" : "=f"(f.x), "=f"(f.y) : "l"(a)); return f;
}
__device__ __forceinline__ ull fma2(ull a, ull b, ull c) {
    ull d; asm("fma.rn.f32x2 %0, %1, %2, %3;" : "=l"(d) : "l"(a), "l"(b), "l"(c)); return d;
}
__device__ __forceinline__ ull relu2(ull a) {
    float2 f = upk(a);
    return pk(fmaxf(f.x, 0.0f), fmaxf(f.y, 0.0f));
}
__device__ __forceinline__ void red4(float* g, float4 v) {
    asm volatile("red.global.add.v4.f32 [%0], {%1,%2,%3,%4};"
                 :: "l"(g), "f"(v.x), "f"(v.y), "f"(v.z), "f"(v.w) : "memory");
}

// ---------------- prep: duplicate W1 weights + dtype detection ----------------
__global__ void k_dup(const int* __restrict__ ei,
                      const float* __restrict__ W1l,
                      const float* __restrict__ W1r) {
    int i = blockIdx.x * 256 + threadIdx.x;
    if (i < DIN * DH) {
        float a = W1l[i], b = W1r[i];
        g_W1lD[i] = pk(a, a);
        g_W1rD[i] = pk(b, b);
    }
    if (blockIdx.x == 0 && threadIdx.x < 32) {
        int lane = threadIdx.x;
        int ok = (ei[2 * lane + 1] == 0) && (ei[2 * lane + 65] == 0)
              && (ei[2 * lane + 129] == 0) && (ei[2 * lane + 193] == 0);
        unsigned all = __all_sync(0xffffffffu, ok);
        if (lane == 0) g_is64 = all ? 1 : 0;
    }
}

// ---------------- layer-1 edge aggregation + degree (smem-staged indices) ----------------
// 128 edges per block; 256 threads x 12 iterations cover 128 edges x 24 float4 chunks.
__global__ void __launch_bounds__(256) k_agg_x(const int* __restrict__ ei32,
                                               const long long* __restrict__ ei64,
                                               const float* __restrict__ x) {
    __shared__ int ss[EPB1], sd[EPB1];
    const int tid = threadIdx.x;
    const int e0  = blockIdx.x * EPB1;

    if (tid < EPB1) {
        int e = e0 + tid;
        int s, d;
        if (g_is64) { s = (int)ei64[e]; d = (int)ei64[NE + e]; }
        else        { s = ei32[e];      d = ei32[NE + e]; }
        ss[tid] = s;
        sd[tid] = d;
        atomicAdd(&g_small[OFF_DEG + d], 1.0f);
    }
    __syncthreads();

#pragma unroll
    for (int i = 0; i < 12; i++) {
        int idx = i * 256 + tid;           // 0..3071 = 128 edges x 24 chunks
        int e = idx / 24;
        int c = idx - e * 24;
        const float4 v = ((const float4*)(x + (size_t)ss[e] * DIN))[c];
        red4(g_agg1 + (size_t)sd[e] * DIN + 4 * c, v);
    }
}

// ---------------- fused GEMMs: 64 rows/block, register-tiled, dup-weight loads ----------------
__global__ void __launch_bounds__(256) k_fused(
        const float* __restrict__ x,
        const float* __restrict__ b1,
        const float* __restrict__ W2l,
        const float* __restrict__ W2r) {

    __shared__ __align__(16) char sm[49152];
    float* aspF = reinterpret_cast<float*>(sm);                 // [96][64]
    float* xspF = aspF + 96 * 64;                               // [96][64]
    ull*   hsT  = reinterpret_cast<ull*>(sm);                   // [32][128]
    float* wsTk = reinterpret_cast<float*>(sm + 32768);         // [128][32]

    const int tid  = threadIdx.x;
    const int row0 = blockIdx.x * RB;

    // staging: thread t -> row r = t>>2, k-chunk (t&3)*24; swizzle ull2-chunks mod 16
    {
        int r  = tid >> 2;
        int k0 = (tid & 3) * 24;
        int gnode = row0 + r;
        int q = r >> 2, lane = r & 3;
        if (gnode < NN) {
            float iv = 1.0f / fmaxf(g_small[OFF_DEG + gnode], 1.0f);
            const float* pa = g_agg1 + (size_t)gnode * DIN + k0;
            const float* px = x + (size_t)gnode * DIN + k0;
#pragma unroll
            for (int i = 0; i < 24; i += 4) {
                float4 a4 = *(const float4*)(pa + i);
                float4 x4 = *(const float4*)(px + i);
#pragma unroll
                for (int kk = 0; kk < 4; kk++) {
                    int k = k0 + i + kk;
                    int pos = k * 64 + (((q + k) & 15) << 2) + lane;
                    aspF[pos] = ((const float*)&a4)[kk] * iv;
                    xspF[pos] = ((const float*)&x4)[kk];
                }
            }
        } else {
#pragma unroll
            for (int i = 0; i < 24; i++) {
                int k = k0 + i;
                int pos = k * 64 + (((q + k) & 15) << 2) + lane;
                aspF[pos] = 0.0f;
                xspF[pos] = 0.0f;
            }
        }
    }
    __syncthreads();

    // stage A: thread (rg = tid>>5, cg = tid&31): rows 8rg..8rg+7, cols 4cg..4cg+3
    const int cg = tid & 31;
    const int rg = tid >> 5;

    ull acc[4][4];
    {
        float4 b4 = *(const float4*)(b1 + 4 * cg);
#pragma unroll
        for (int c = 0; c < 4; c++) {
            float bv = ((const float*)&b4)[c];
            ull bp = pk(bv, bv);
#pragma unroll
            for (int p = 0; p < 4; p++) acc[p][c] = bp;
        }
    }

    const ulonglong2* aU2 = (const ulonglong2*)aspF;   // [96][16]
    const ulonglong2* xU2 = (const ulonglong2*)xspF;

#pragma unroll 2
    for (int k = 0; k < DIN; k++) {
        int q0 = (2 * rg + k) & 15;
        int q1 = (2 * rg + 1 + k) & 15;
        ulonglong2 a01 = aU2[k * 16 + q0];
        ulonglong2 a23 = aU2[k * 16 + q1];
        ulonglong2 x01 = xU2[k * 16 + q0];
        ulonglong2 x23 = xU2[k * 16 + q1];
        // duplicated weights: no packing MOVs in the hot loop
        const ulonglong2* wlD = (const ulonglong2*)(g_W1lD + k * DH + 4 * cg);
        const ulonglong2* wrD = (const ulonglong2*)(g_W1rD + k * DH + 4 * cg);
        ulonglong2 wl01 = __ldg(wlD), wl23 = __ldg(wlD + 1);
        ulonglong2 wr01 = __ldg(wrD), wr23 = __ldg(wrD + 1);

        acc[0][0] = fma2(a01.x, wl01.x, acc[0][0]);
        acc[0][0] = fma2(x01.x, wr01.x, acc[0][0]);
        acc[1][0] = fma2(a01.y, wl01.x, acc[1][0]);
        acc[1][0] = fma2(x01.y, wr01.x, acc[1][0]);
        acc[2][0] = fma2(a23.x, wl01.x, acc[2][0]);
        acc[2][0] = fma2(x23.x, wr01.x, acc[2][0]);
        acc[3][0] = fma2(a23.y, wl01.x, acc[3][0]);
        acc[3][0] = fma2(x23.y, wr01.x, acc[3][0]);

        acc[0][1] = fma2(a01.x, wl01.y, acc[0][1]);
        acc[0][1] = fma2(x01.x, wr01.y, acc[0][1]);
        acc[1][1] = fma2(a01.y, wl01.y, acc[1][1]);
        acc[1][1] = fma2(x01.y, wr01.y, acc[1][1]);
        acc[2][1] = fma2(a23.x, wl01.y, acc[2][1]);
        acc[2][1] = fma2(x23.x, wr01.y, acc[2][1]);
        acc[3][1] = fma2(a23.y, wl01.y, acc[3][1]);
        acc[3][1] = fma2(x23.y, wr01.y, acc[3][1]);

        acc[0][2] = fma2(a01.x, wl23.x, acc[0][2]);
        acc[0][2] = fma2(x01.x, wr23.x, acc[0][2]);
        acc[1][2] = fma2(a01.y, wl23.x, acc[1][2]);
        acc[1][2] = fma2(x01.y, wr23.x, acc[1][2]);
        acc[2][2] = fma2(a23.x, wl23.x, acc[2][2]);
        acc[2][2] = fma2(x23.x, wr23.x, acc[2][2]);
        acc[3][2] = fma2(a23.y, wl23.x, acc[3][2]);
        acc[3][2] = fma2(x23.y, wr23.x, acc[3][2]);

        acc[0][3] = fma2(a01.x, wl23.y, acc[0][3]);
        acc[0][3] = fma2(x01.x, wr23.y, acc[0][3]);
        acc[1][3] = fma2(a01.y, wl23.y, acc[1][3]);
        acc[1][3] = fma2(x01.y, wr23.y, acc[1][3]);
        acc[2][3] = fma2(a23.x, wl23.y, acc[2][3]);
        acc[2][3] = fma2(x23.x, wr23.y, acc[2][3]);
        acc[3][3] = fma2(a23.y, wl23.y, acc[3][3]);
        acc[3][3] = fma2(x23.y, wr23.y, acc[3][3]);
    }
    __syncthreads();   // asp/xsp reads complete before phase-2 overwrite

    // relu + store h (packed pairs) + load W2 (k-major)
#pragma unroll
    for (int p = 0; p < 4; p++) {
        ulonglong2* dstp = (ulonglong2*)(hsT + (size_t)(4 * rg + p) * DH + 4 * cg);
        ulonglong2 v0, v1;
        v0.x = relu2(acc[p][0]); v0.y = relu2(acc[p][1]);
        v1.x = relu2(acc[p][2]); v1.y = relu2(acc[p][3]);
        dstp[0] = v0; dstp[1] = v1;
    }
    for (int i = tid; i < DH * DOUT; i += 256) {
        int k = i >> 4, j = i & 15;
        wsTk[k * 32 + j]      = W2l[i];
        wsTk[k * 32 + 16 + j] = W2r[i];
    }
    __syncthreads();

    // stage B: thread (pg = tid>>4, c2 = tid&15): pairs {pg, pg+16}, cols {c2, c2+16}
    const int c2 = tid & 15;
    const int pg = tid >> 4;
    const ulonglong2* h0p = (const ulonglong2*)(hsT + (size_t)pg * DH);
    const ulonglong2* h1p = (const ulonglong2*)(hsT + (size_t)(pg + 16) * DH);

    ull a00 = 0, a01v = 0, a10 = 0, a11v = 0;
#pragma unroll 4
    for (int k4 = 0; k4 < DH / 4; k4++) {
        ulonglong2 hA0 = h0p[2 * k4], hA1 = h0p[2 * k4 + 1];
        ulonglong2 hB0 = h1p[2 * k4], hB1 = h1p[2 * k4 + 1];
#pragma unroll
        for (int kk = 0; kk < 4; kk++) {
            int k = 4 * k4 + kk;
            float w0 = wsTk[k * 32 + c2];
            float w1 = wsTk[k * 32 + 16 + c2];
            ull w0p = pk(w0, w0), w1p = pk(w1, w1);
            ull hA = (kk == 0) ? hA0.x : (kk == 1) ? hA0.y : (kk == 2) ? hA1.x : hA1.y;
            ull hB = (kk == 0) ? hB0.x : (kk == 1) ? hB0.y : (kk == 2) ? hB1.x : hB1.y;
            a00  = fma2(hA, w0p, a00);
            a01v = fma2(hA, w1p, a01v);
            a10  = fma2(hB, w0p, a10);
            a11v = fma2(hB, w1p, a11v);
        }
    }

    {
        int rA0 = row0 + 2 * pg,        rA1 = rA0 + 1;
        int rB0 = row0 + 2 * (pg + 16), rB1 = rB0 + 1;
        float2 f;
        f = upk(a00);
        if (rA0 < NN) g_r[(size_t)rA0 * 32 + c2] = f.x;
        if (rA1 < NN) g_r[(size_t)rA1 * 32 + c2] = f.y;
        f = upk(a01v);
        if (rA0 < NN) g_r[(size_t)rA0 * 32 + 16 + c2] = f.x;
        if (rA1 < NN) g_r[(size_t)rA1 * 32 + 16 + c2] = f.y;
        f = upk(a10);
        if (rB0 < NN) g_r[(size_t)rB0 * 32 + c2] = f.x;
        if (rB1 < NN) g_r[(size_t)rB1 * 32 + c2] = f.y;
        f = upk(a11v);
        if (rB0 < NN) g_r[(size_t)rB0 * 32 + 16 + c2] = f.x;
        if (rB1 < NN) g_r[(size_t)rB1 * 32 + 16 + c2] = f.y;
    }
}

// ---------------- layer-2 edge aggregation (flat) ----------------
__global__ void k_agg_p(const int* __restrict__ ei32,
                        const long long* __restrict__ ei64) {
    int gid = blockIdx.x * blockDim.x + threadIdx.x;
    if (gid >= NE * 4) return;
    int e = gid >> 2;
    int c = gid & 3;
    int src, dst;
    if (g_is64) { src = (int)ei64[e]; dst = (int)ei64[NE + e]; }
    else        { src = ei32[e];      dst = ei32[NE + e]; }

    const float4 v = ((const float4*)(g_r + (size_t)src * 32))[c];
    red4(g_small + OFF_AGG2 + (size_t)dst * DOUT + 4 * c, v);
}

// ---------------- epilogue: softmax(agg2/deg + b2 + q) ----------------
__global__ void k_finalize(const float* __restrict__ b2,
                           float* __restrict__ out) {
    int row = blockIdx.x * blockDim.x + threadIdx.x;
    if (row >= NN) return;
    float inv = 1.0f / fmaxf(g_small[OFF_DEG + row], 1.0f);

    float v[DOUT];
    float mx = -1e30f;
#pragma unroll
    for (int j = 0; j < DOUT; j++) {
        v[j] = g_small[OFF_AGG2 + (size_t)row * DOUT + j] * inv + b2[j]
             + g_r[(size_t)row * 32 + 16 + j];
        mx = fmaxf(mx, v[j]);
    }
    float s = 0.f;
#pragma unroll
    for (int j = 0; j < DOUT; j++) {
        v[j] = __expf(v[j] - mx);
        s += v[j];
    }
    float is = 1.0f / s;
#pragma unroll
    for (int j = 0; j < DOUT; j++)
        out[(size_t)row * DOUT + j] = v[j] * is;
}

// ---------------- launch ----------------
extern "C" void kernel_launch(void* const* d_in, const int* in_sizes, int n_in,
                              void* d_out, int out_size) {
    const float*     x    = (const float*)d_in[0];
    const int*       ei32 = (const int*)d_in[1];
    const long long* ei64 = (const long long*)d_in[1];
    const float*     W1l  = (const float*)d_in[2];
    const float*     b1   = (const float*)d_in[3];
    const float*     W1r  = (const float*)d_in[4];
    const float*     W2l  = (const float*)d_in[5];
    const float*     b2   = (const float*)d_in[6];
    const float*     W2r  = (const float*)d_in[7];
    float* out = (float*)d_out;

    static cudaStream_t s1 = nullptr;
    static cudaEvent_t  evFork = nullptr, evJoin = nullptr;
    if (!s1) {
        cudaStreamCreateWithFlags(&s1, cudaStreamNonBlocking);
        cudaEventCreateWithFlags(&evFork, cudaEventDisableTiming);
        cudaEventCreateWithFlags(&evJoin, cudaEventDisableTiming);
    }

    void *smallp, *agg1p;
    cudaGetSymbolAddress(&smallp, g_small);
    cudaGetSymbolAddress(&agg1p,  g_agg1);

    // prep (weight dup + dtype detect) and small zero, then aggregation.
    // g_agg1 is already zero: statically on call 0, re-zeroed at end of every call.
    cudaMemsetAsync(smallp, 0, sizeof(float) * SMALL_TOTAL, 0);
    k_dup   <<<(DIN * DH + 255) / 256, 256>>>(ei32, W1l, W1r);
    k_agg_x <<<NE / EPB1, 256>>>(ei32, ei64, x);
    k_fused <<<(NN + RB - 1) / RB, 256>>>(x, b1, W2l, W2r);

    // fork: re-zero g_agg1 for the NEXT call, overlapped with agg_p + finalize
    cudaEventRecord(evFork, 0);
    cudaStreamWaitEvent(s1, evFork, 0);
    cudaMemsetAsync(agg1p, 0, sizeof(float) * NN * DIN, s1);
    cudaEventRecord(evJoin, s1);

    k_agg_p   <<<(NE * 4 + 255) / 256, 256>>>(ei32, ei64);
    k_finalize<<<(NN + 127) / 128, 128>>>(b2, out);

    // join: launch must not complete before the re-zero does
    cudaStreamWaitEvent(0, evJoin, 0);
}

// round 14
// speedup vs baseline: 1.1628x; 1.1628x over previous
#include <cuda_runtime.h>
#include <cstdint>

#define NN   50000
#define NE   800000
#define DIN  96
#define DH   128
#define DOUT 16
#define RB   64          // rows per fused block
#define EPB1 64          // edges per block, layer-1 agg

typedef unsigned long long ull;

// ---------------- scratch ----------------
// g_agg1: zeroed at END of each launch (overlapped); statically zero for call 0.
__device__ __align__(16) float g_agg1[NN * DIN];
// g_small: [deg | agg2], zeroed at start (3.4 MB, ~1 us)
#define OFF_DEG  0
#define OFF_AGG2 NN
#define SMALL_TOTAL (NN + NN * DOUT)
__device__ __align__(16) float g_small[SMALL_TOTAL];
__device__ __align__(16) float g_r[NN * 32];     // [p | q] = h @ [W2_l | W2_r]
__device__ int g_is64;

// ---------------- f32x2 packed helpers (sm_100+) ----------------
__device__ __forceinline__ ull pk(float a, float b) {
    ull r; asm("mov.b64 %0, {%1,%2};" : "=l"(r) : "f"(a), "f"(b)); return r;
}
__device__ __forceinline__ float2 upk(ull a) {
    float2 f; asm("mov.b64 {%0,%1}, %2;" : "=f"(f.x), "=f"(f.y) : "l"(a)); return f;
}
__device__ __forceinline__ ull fma2(ull a, ull b, ull c) {
    ull d; asm("fma.rn.f32x2 %0, %1, %2, %3;" : "=l"(d) : "l"(a), "l"(b), "l"(c)); return d;
}
__device__ __forceinline__ ull relu2(ull a) {
    float2 f = upk(a);
    return pk(fmaxf(f.x, 0.0f), fmaxf(f.y, 0.0f));
}
__device__ __forceinline__ void red4(float* g, float4 v) {
    asm volatile("red.global.add.v4.f32 [%0], {%1,%2,%3,%4};"
                 :: "l"(g), "f"(v.x), "f"(v.y), "f"(v.z), "f"(v.w) : "memory");
}

// ---------------- dtype detection (parallel) ----------------
__global__ void k_detect(const int* __restrict__ ei) {
    int lane = threadIdx.x;                  // 32 threads
    int ok = (ei[2 * lane + 1] == 0) && (ei[2 * lane + 65] == 0)
          && (ei[2 * lane + 129] == 0) && (ei[2 * lane + 193] == 0);
    unsigned all = __all_sync(0xffffffffu, ok);
    if (lane == 0) g_is64 = all ? 1 : 0;
}

// ---------------- layer-1 edge aggregation + degree (smem-staged indices) ----------------
// 64 edges per block; 256 threads x 6 iterations cover 64 edges x 24 float4 chunks.
__global__ void __launch_bounds__(256) k_agg_x(const int* __restrict__ ei32,
                                               const long long* __restrict__ ei64,
                                               const float* __restrict__ x) {
    __shared__ int ss[EPB1], sd[EPB1];
    const int tid = threadIdx.x;
    const int e0  = blockIdx.x * EPB1;

    if (tid < EPB1) {
        int e = e0 + tid;
        int s, d;
        if (g_is64) { s = (int)ei64[e]; d = (int)ei64[NE + e]; }
        else        { s = ei32[e];      d = ei32[NE + e]; }
        ss[tid] = s;
        sd[tid] = d;
        atomicAdd(&g_small[OFF_DEG + d], 1.0f);
    }
    __syncthreads();

#pragma unroll
    for (int i = 0; i < 6; i++) {
        int idx = i * 256 + tid;           // 0..1535 = 64 edges x 24 chunks
        int e = idx / 24;
        int c = idx - e * 24;
        const float4 v = ((const float4*)(x + (size_t)ss[e] * DIN))[c];
        red4(g_agg1 + (size_t)sd[e] * DIN + 4 * c, v);
    }
}

// ---------------- fused GEMMs: 64 rows/block, register-tiled 8 rows x 4 cols ----------------
__global__ void __launch_bounds__(256) k_fused(
        const float* __restrict__ x,
        const float* __restrict__ W1l,
        const float* __restrict__ b1,
        const float* __restrict__ W1r,
        const float* __restrict__ W2l,
        const float* __restrict__ W2r) {

    __shared__ __align__(16) char sm[49152];
    float* aspF = reinterpret_cast<float*>(sm);                 // [96][64]
    float* xspF = aspF + 96 * 64;                               // [96][64]
    ull*   hsT  = reinterpret_cast<ull*>(sm);                   // [32][128]
    float* wsTk = reinterpret_cast<float*>(sm + 32768);         // [128][32]

    const int tid  = threadIdx.x;
    const int row0 = blockIdx.x * RB;

    // staging: thread t -> row r = t>>2, k-chunk (t&3)*24; swizzle ull2-chunks mod 16
    {
        int r  = tid >> 2;
        int k0 = (tid & 3) * 24;
        int gnode = row0 + r;
        int q = r >> 2, lane = r & 3;
        if (gnode < NN) {
            float iv = 1.0f / fmaxf(g_small[OFF_DEG + gnode], 1.0f);
            const float* pa = g_agg1 + (size_t)gnode * DIN + k0;
            const float* px = x + (size_t)gnode * DIN + k0;
#pragma unroll
            for (int i = 0; i < 24; i += 4) {
                float4 a4 = *(const float4*)(pa + i);
                float4 x4 = *(const float4*)(px + i);
#pragma unroll
                for (int kk = 0; kk < 4; kk++) {
                    int k = k0 + i + kk;
                    int pos = k * 64 + (((q + k) & 15) << 2) + lane;
                    aspF[pos] = ((const float*)&a4)[kk] * iv;
                    xspF[pos] = ((const float*)&x4)[kk];
                }
            }
        } else {
#pragma unroll
            for (int i = 0; i < 24; i++) {
                int k = k0 + i;
                int pos = k * 64 + (((q + k) & 15) << 2) + lane;
                aspF[pos] = 0.0f;
                xspF[pos] = 0.0f;
            }
        }
    }
    __syncthreads();

    // stage A: thread (rg = tid>>5, cg = tid&31): rows 8rg..8rg+7, cols 4cg..4cg+3
    const int cg = tid & 31;
    const int rg = tid >> 5;

    ull acc[4][4];
    {
        float4 b4 = *(const float4*)(b1 + 4 * cg);
#pragma unroll
        for (int c = 0; c < 4; c++) {
            float bv = ((const float*)&b4)[c];
            ull bp = pk(bv, bv);
#pragma unroll
            for (int p = 0; p < 4; p++) acc[p][c] = bp;
        }
    }

    const ulonglong2* aU2 = (const ulonglong2*)aspF;   // [96][16]
    const ulonglong2* xU2 = (const ulonglong2*)xspF;

#pragma unroll 2
    for (int k = 0; k < DIN; k++) {
        int q0 = (2 * rg + k) & 15;
        int q1 = (2 * rg + 1 + k) & 15;
        ulonglong2 a01 = aU2[k * 16 + q0];
        ulonglong2 a23 = aU2[k * 16 + q1];
        ulonglong2 x01 = xU2[k * 16 + q0];
        ulonglong2 x23 = xU2[k * 16 + q1];
        float4 wl4 = __ldg((const float4*)(W1l + k * DH + 4 * cg));
        float4 wr4 = __ldg((const float4*)(W1r + k * DH + 4 * cg));
#pragma unroll
        for (int c = 0; c < 4; c++) {
            float wlv = ((const float*)&wl4)[c];
            float wrv = ((const float*)&wr4)[c];
            ull wl2 = pk(wlv, wlv);
            ull wr2 = pk(wrv, wrv);
            acc[0][c] = fma2(a01.x, wl2, acc[0][c]);
            acc[0][c] = fma2(x01.x, wr2, acc[0][c]);
            acc[1][c] = fma2(a01.y, wl2, acc[1][c]);
            acc[1][c] = fma2(x01.y, wr2, acc[1][c]);
            acc[2][c] = fma2(a23.x, wl2, acc[2][c]);
            acc[2][c] = fma2(x23.x, wr2, acc[2][c]);
            acc[3][c] = fma2(a23.y, wl2, acc[3][c]);
            acc[3][c] = fma2(x23.y, wr2, acc[3][c]);
        }
    }
    __syncthreads();   // asp/xsp reads complete before phase-2 overwrite

    // relu + store h (packed pairs) + load W2 (k-major)
#pragma unroll
    for (int p = 0; p < 4; p++) {
        ulonglong2* dstp = (ulonglong2*)(hsT + (size_t)(4 * rg + p) * DH + 4 * cg);
        ulonglong2 v0, v1;
        v0.x = relu2(acc[p][0]); v0.y = relu2(acc[p][1]);
        v1.x = relu2(acc[p][2]); v1.y = relu2(acc[p][3]);
        dstp[0] = v0; dstp[1] = v1;
    }
    for (int i = tid; i < DH * DOUT; i += 256) {
        int k = i >> 4, j = i & 15;
        wsTk[k * 32 + j]      = W2l[i];
        wsTk[k * 32 + 16 + j] = W2r[i];
    }
    __syncthreads();

    // stage B: thread (pg = tid>>4, c2 = tid&15): pairs {pg, pg+16}, cols {c2, c2+16}
    const int c2 = tid & 15;
    const int pg = tid >> 4;
    const ulonglong2* h0p = (const ulonglong2*)(hsT + (size_t)pg * DH);
    const ulonglong2* h1p = (const ulonglong2*)(hsT + (size_t)(pg + 16) * DH);

    ull a00 = 0, a01v = 0, a10 = 0, a11v = 0;
#pragma unroll 4
    for (int k4 = 0; k4 < DH / 4; k4++) {
        ulonglong2 hA0 = h0p[2 * k4], hA1 = h0p[2 * k4 + 1];
        ulonglong2 hB0 = h1p[2 * k4], hB1 = h1p[2 * k4 + 1];
#pragma unroll
        for (int kk = 0; kk < 4; kk++) {
            int k = 4 * k4 + kk;
            float w0 = wsTk[k * 32 + c2];
            float w1 = wsTk[k * 32 + 16 + c2];
            ull w0p = pk(w0, w0), w1p = pk(w1, w1);
            ull hA = (kk == 0) ? hA0.x : (kk == 1) ? hA0.y : (kk == 2) ? hA1.x : hA1.y;
            ull hB = (kk == 0) ? hB0.x : (kk == 1) ? hB0.y : (kk == 2) ? hB1.x : hB1.y;
            a00  = fma2(hA, w0p, a00);
            a01v = fma2(hA, w1p, a01v);
            a10  = fma2(hB, w0p, a10);
            a11v = fma2(hB, w1p, a11v);
        }
    }

    {
        int rA0 = row0 + 2 * pg,        rA1 = rA0 + 1;
        int rB0 = row0 + 2 * (pg + 16), rB1 = rB0 + 1;
        float2 f;
        f = upk(a00);
        if (rA0 < NN) g_r[(size_t)rA0 * 32 + c2] = f.x;
        if (rA1 < NN) g_r[(size_t)rA1 * 32 + c2] = f.y;
        f = upk(a01v);
        if (rA0 < NN) g_r[(size_t)rA0 * 32 + 16 + c2] = f.x;
        if (rA1 < NN) g_r[(size_t)rA1 * 32 + 16 + c2] = f.y;
        f = upk(a10);
        if (rB0 < NN) g_r[(size_t)rB0 * 32 + c2] = f.x;
        if (rB1 < NN) g_r[(size_t)rB1 * 32 + c2] = f.y;
        f = upk(a11v);
        if (rB0 < NN) g_r[(size_t)rB0 * 32 + 16 + c2] = f.x;
        if (rB1 < NN) g_r[(size_t)rB1 * 32 + 16 + c2] = f.y;
    }
}

// ---------------- layer-2 edge aggregation: ONE thread per edge ----------------
// 2 index LDGs + 4 LDG.128 + 4 RED.128 per edge (was 16 LSU ops with 4 thr/edge)
__global__ void __launch_bounds__(256) k_agg_p(const int* __restrict__ ei32,
                                               const long long* __restrict__ ei64) {
    int e = blockIdx.x * blockDim.x + threadIdx.x;
    if (e >= NE) return;
    int src, dst;
    if (g_is64) { src = (int)ei64[e]; dst = (int)ei64[NE + e]; }
    else        { src = ei32[e];      dst = ei32[NE + e]; }

    const float4* pr = (const float4*)(g_r + (size_t)src * 32);   // p = first 16
    float* o = g_small + OFF_AGG2 + (size_t)dst * DOUT;
    float4 v0 = pr[0], v1 = pr[1], v2 = pr[2], v3 = pr[3];
    red4(o,      v0);
    red4(o + 4,  v1);
    red4(o + 8,  v2);
    red4(o + 12, v3);
}

// ---------------- epilogue: softmax(agg2/deg + b2 + q) ----------------
__global__ void k_finalize(const float* __restrict__ b2,
                           float* __restrict__ out) {
    int row = blockIdx.x * blockDim.x + threadIdx.x;
    if (row >= NN) return;
    float inv = 1.0f / fmaxf(g_small[OFF_DEG + row], 1.0f);

    float v[DOUT];
    float mx = -1e30f;
#pragma unroll
    for (int j = 0; j < DOUT; j++) {
        v[j] = g_small[OFF_AGG2 + (size_t)row * DOUT + j] * inv + b2[j]
             + g_r[(size_t)row * 32 + 16 + j];
        mx = fmaxf(mx, v[j]);
    }
    float s = 0.f;
#pragma unroll
    for (int j = 0; j < DOUT; j++) {
        v[j] = __expf(v[j] - mx);
        s += v[j];
    }
    float is = 1.0f / s;
#pragma unroll
    for (int j = 0; j < DOUT; j++)
        out[(size_t)row * DOUT + j] = v[j] * is;
}

// ---------------- launch ----------------
extern "C" void kernel_launch(void* const* d_in, const int* in_sizes, int n_in,
                              void* d_out, int out_size) {
    const float*     x    = (const float*)d_in[0];
    const int*       ei32 = (const int*)d_in[1];
    const long long* ei64 = (const long long*)d_in[1];
    const float*     W1l  = (const float*)d_in[2];
    const float*     b1   = (const float*)d_in[3];
    const float*     W1r  = (const float*)d_in[4];
    const float*     W2l  = (const float*)d_in[5];
    const float*     b2   = (const float*)d_in[6];
    const float*     W2r  = (const float*)d_in[7];
    float* out = (float*)d_out;

    static cudaStream_t s1 = nullptr;
    static cudaEvent_t  evFork = nullptr, evJoin = nullptr;
    if (!s1) {
        cudaStreamCreateWithFlags(&s1, cudaStreamNonBlocking);
        cudaEventCreateWithFlags(&evFork, cudaEventDisableTiming);
        cudaEventCreateWithFlags(&evJoin, cudaEventDisableTiming);
    }

    void *smallp, *agg1p;
    cudaGetSymbolAddress(&smallp, g_small);
    cudaGetSymbolAddress(&agg1p,  g_agg1);

    // small zero (deg+agg2, 3.4 MB) + detect, then the big aggregation.
    // g_agg1 is already zero: statically on call 0, re-zeroed at end of every call.
    cudaMemsetAsync(smallp, 0, sizeof(float) * SMALL_TOTAL, 0);
    k_detect<<<1, 32>>>(ei32);
    k_agg_x <<<NE / EPB1, 256>>>(ei32, ei64, x);
    k_fused <<<(NN + RB - 1) / RB, 256>>>(x, W1l, b1, W1r, W2l, W2r);

    // fork: re-zero g_agg1 for the NEXT call, overlapped with agg_p + finalize
    cudaEventRecord(evFork, 0);
    cudaStreamWaitEvent(s1, evFork, 0);
    cudaMemsetAsync(agg1p, 0, sizeof(float) * NN * DIN, s1);
    cudaEventRecord(evJoin, s1);

    k_agg_p   <<<(NE + 255) / 256, 256>>>(ei32, ei64);
    k_finalize<<<(NN + 127) / 128, 128>>>(b2, out);

    // join: launch must not complete before the re-zero does
    cudaStreamWaitEvent(0, evJoin, 0);
}

// round 15
// speedup vs baseline: 1.2428x; 1.0688x over previous
#include <cuda_runtime.h>
#include <cstdint>

#define NN   50000
#define NE   800000
#define DIN  96
#define DH   128
#define DOUT 16
#define RB   64          // rows per fused block
#define EPB1 128         // edges per block, layer-1 agg

typedef unsigned long long ull;

// ---------------- scratch ----------------
// g_agg1: zeroed at END of each launch (overlapped); statically zero for call 0.
__device__ __align__(16) float g_agg1[NN * DIN];
// g_small: [deg | agg2], zeroed at start (3.4 MB, ~1 us)
#define OFF_DEG  0
#define OFF_AGG2 NN
#define SMALL_TOTAL (NN + NN * DOUT)
__device__ __align__(16) float g_small[SMALL_TOTAL];
__device__ __align__(16) float g_r[NN * 32];     // [p | q] = h @ [W2_l | W2_r]
__device__ int g_is64;

// ---------------- f32x2 packed helpers (sm_100+) ----------------
__device__ __forceinline__ ull pk(float a, float b) {
    ull r; asm("mov.b64 %0, {%1,%2};" : "=l"(r) : "f"(a), "f"(b)); return r;
}
__device__ __forceinline__ float2 upk(ull a) {
    float2 f; asm("mov.b64 {%0,%1}, %2;" : "=f"(f.x), "=f"(f.y) : "l"(a)); return f;
}
__device__ __forceinline__ ull fma2(ull a, ull b, ull c) {
    ull d; asm("fma.rn.f32x2 %0, %1, %2, %3;" : "=l"(d) : "l"(a), "l"(b), "l"(c)); return d;
}
__device__ __forceinline__ ull relu2(ull a) {
    float2 f = upk(a);
    return pk(fmaxf(f.x, 0.0f), fmaxf(f.y, 0.0f));
}
__device__ __forceinline__ void red4(float* g, float4 v) {
    asm volatile("red.global.add.v4.f32 [%0], {%1,%2,%3,%4};"
                 :: "l"(g), "f"(v.x), "f"(v.y), "f"(v.z), "f"(v.w) : "memory");
}

// ---------------- dtype detection (parallel) ----------------
__global__ void k_detect(const int* __restrict__ ei) {
    int lane = threadIdx.x;                  // 32 threads
    int ok = (ei[2 * lane + 1] == 0) && (ei[2 * lane + 65] == 0)
          && (ei[2 * lane + 129] == 0) && (ei[2 * lane + 193] == 0);
    unsigned all = __all_sync(0xffffffffu, ok);
    if (lane == 0) g_is64 = all ? 1 : 0;
}

// ---------------- layer-1 edge aggregation + degree (smem-staged indices) ----------------
// 128 edges per block; 256 threads x 12 iterations cover 128 edges x 24 float4 chunks.
__global__ void __launch_bounds__(256) k_agg_x(const int* __restrict__ ei32,
                                               const long long* __restrict__ ei64,
                                               const float* __restrict__ x) {
    __shared__ int ss[EPB1], sd[EPB1];
    const int tid = threadIdx.x;
    const int e0  = blockIdx.x * EPB1;

    if (tid < EPB1) {
        int e = e0 + tid;
        int s, d;
        if (g_is64) { s = (int)ei64[e]; d = (int)ei64[NE + e]; }
        else        { s = ei32[e];      d = ei32[NE + e]; }
        ss[tid] = s;
        sd[tid] = d;
        atomicAdd(&g_small[OFF_DEG + d], 1.0f);
    }
    __syncthreads();

#pragma unroll
    for (int i = 0; i < 12; i++) {
        int idx = i * 256 + tid;           // 0..3071 = 128 edges x 24 chunks
        int e = idx / 24;
        int c = idx - e * 24;
        const float4 v = ((const float4*)(x + (size_t)ss[e] * DIN))[c];
        red4(g_agg1 + (size_t)sd[e] * DIN + 4 * c, v);
    }
}

// ---------------- fused GEMMs: 64 rows/block, register-tiled 8 rows x 4 cols ----------------
__global__ void __launch_bounds__(256) k_fused(
        const float* __restrict__ x,
        const float* __restrict__ W1l,
        const float* __restrict__ b1,
        const float* __restrict__ W1r,
        const float* __restrict__ W2l,
        const float* __restrict__ W2r) {

    __shared__ __align__(16) char sm[49152];
    float* aspF = reinterpret_cast<float*>(sm);                 // [96][64]
    float* xspF = aspF + 96 * 64;                               // [96][64]
    ull*   hsT  = reinterpret_cast<ull*>(sm);                   // [32][128]
    float* wsTk = reinterpret_cast<float*>(sm + 32768);         // [128][32]

    const int tid  = threadIdx.x;
    const int row0 = blockIdx.x * RB;

    // staging: thread t -> row r = t>>2, k-chunk (t&3)*24; swizzle ull2-chunks mod 16
    {
        int r  = tid >> 2;
        int k0 = (tid & 3) * 24;
        int gnode = row0 + r;
        int q = r >> 2, lane = r & 3;
        if (gnode < NN) {
            float iv = 1.0f / fmaxf(g_small[OFF_DEG + gnode], 1.0f);
            const float* pa = g_agg1 + (size_t)gnode * DIN + k0;
            const float* px = x + (size_t)gnode * DIN + k0;
#pragma unroll
            for (int i = 0; i < 24; i += 4) {
                float4 a4 = *(const float4*)(pa + i);
                float4 x4 = *(const float4*)(px + i);
#pragma unroll
                for (int kk = 0; kk < 4; kk++) {
                    int k = k0 + i + kk;
                    int pos = k * 64 + (((q + k) & 15) << 2) + lane;
                    aspF[pos] = ((const float*)&a4)[kk] * iv;
                    xspF[pos] = ((const float*)&x4)[kk];
                }
            }
        } else {
#pragma unroll
            for (int i = 0; i < 24; i++) {
                int k = k0 + i;
                int pos = k * 64 + (((q + k) & 15) << 2) + lane;
                aspF[pos] = 0.0f;
                xspF[pos] = 0.0f;
            }
        }
    }
    __syncthreads();

    // stage A: thread (rg = tid>>5, cg = tid&31): rows 8rg..8rg+7, cols 4cg..4cg+3
    const int cg = tid & 31;
    const int rg = tid >> 5;

    ull acc[4][4];
    {
        float4 b4 = *(const float4*)(b1 + 4 * cg);
#pragma unroll
        for (int c = 0; c < 4; c++) {
            float bv = ((const float*)&b4)[c];
            ull bp = pk(bv, bv);
#pragma unroll
            for (int p = 0; p < 4; p++) acc[p][c] = bp;
        }
    }

    const ulonglong2* aU2 = (const ulonglong2*)aspF;   // [96][16]
    const ulonglong2* xU2 = (const ulonglong2*)xspF;

#pragma unroll 2
    for (int k = 0; k < DIN; k++) {
        int q0 = (2 * rg + k) & 15;
        int q1 = (2 * rg + 1 + k) & 15;
        ulonglong2 a01 = aU2[k * 16 + q0];
        ulonglong2 a23 = aU2[k * 16 + q1];
        ulonglong2 x01 = xU2[k * 16 + q0];
        ulonglong2 x23 = xU2[k * 16 + q1];
        float4 wl4 = __ldg((const float4*)(W1l + k * DH + 4 * cg));
        float4 wr4 = __ldg((const float4*)(W1r + k * DH + 4 * cg));
#pragma unroll
        for (int c = 0; c < 4; c++) {
            float wlv = ((const float*)&wl4)[c];
            float wrv = ((const float*)&wr4)[c];
            ull wl2 = pk(wlv, wlv);
            ull wr2 = pk(wrv, wrv);
            acc[0][c] = fma2(a01.x, wl2, acc[0][c]);
            acc[0][c] = fma2(x01.x, wr2, acc[0][c]);
            acc[1][c] = fma2(a01.y, wl2, acc[1][c]);
            acc[1][c] = fma2(x01.y, wr2, acc[1][c]);
            acc[2][c] = fma2(a23.x, wl2, acc[2][c]);
            acc[2][c] = fma2(x23.x, wr2, acc[2][c]);
            acc[3][c] = fma2(a23.y, wl2, acc[3][c]);
            acc[3][c] = fma2(x23.y, wr2, acc[3][c]);
        }
    }
    __syncthreads();   // asp/xsp reads complete before phase-2 overwrite

    // relu + store h (packed pairs) + load W2 (k-major)
#pragma unroll
    for (int p = 0; p < 4; p++) {
        ulonglong2* dstp = (ulonglong2*)(hsT + (size_t)(4 * rg + p) * DH + 4 * cg);
        ulonglong2 v0, v1;
        v0.x = relu2(acc[p][0]); v0.y = relu2(acc[p][1]);
        v1.x = relu2(acc[p][2]); v1.y = relu2(acc[p][3]);
        dstp[0] = v0; dstp[1] = v1;
    }
    for (int i = tid; i < DH * DOUT; i += 256) {
        int k = i >> 4, j = i & 15;
        wsTk[k * 32 + j]      = W2l[i];
        wsTk[k * 32 + 16 + j] = W2r[i];
    }
    __syncthreads();

    // stage B: thread (pg = tid>>4, c2 = tid&15): pairs {pg, pg+16}, cols {c2, c2+16}
    const int c2 = tid & 15;
    const int pg = tid >> 4;
    const ulonglong2* h0p = (const ulonglong2*)(hsT + (size_t)pg * DH);
    const ulonglong2* h1p = (const ulonglong2*)(hsT + (size_t)(pg + 16) * DH);

    ull a00 = 0, a01v = 0, a10 = 0, a11v = 0;
#pragma unroll 4
    for (int k4 = 0; k4 < DH / 4; k4++) {
        ulonglong2 hA0 = h0p[2 * k4], hA1 = h0p[2 * k4 + 1];
        ulonglong2 hB0 = h1p[2 * k4], hB1 = h1p[2 * k4 + 1];
#pragma unroll
        for (int kk = 0; kk < 4; kk++) {
            int k = 4 * k4 + kk;
            float w0 = wsTk[k * 32 + c2];
            float w1 = wsTk[k * 32 + 16 + c2];
            ull w0p = pk(w0, w0), w1p = pk(w1, w1);
            ull hA = (kk == 0) ? hA0.x : (kk == 1) ? hA0.y : (kk == 2) ? hA1.x : hA1.y;
            ull hB = (kk == 0) ? hB0.x : (kk == 1) ? hB0.y : (kk == 2) ? hB1.x : hB1.y;
            a00  = fma2(hA, w0p, a00);
            a01v = fma2(hA, w1p, a01v);
            a10  = fma2(hB, w0p, a10);
            a11v = fma2(hB, w1p, a11v);
        }
    }

    {
        int rA0 = row0 + 2 * pg,        rA1 = rA0 + 1;
        int rB0 = row0 + 2 * (pg + 16), rB1 = rB0 + 1;
        float2 f;
        f = upk(a00);
        if (rA0 < NN) g_r[(size_t)rA0 * 32 + c2] = f.x;
        if (rA1 < NN) g_r[(size_t)rA1 * 32 + c2] = f.y;
        f = upk(a01v);
        if (rA0 < NN) g_r[(size_t)rA0 * 32 + 16 + c2] = f.x;
        if (rA1 < NN) g_r[(size_t)rA1 * 32 + 16 + c2] = f.y;
        f = upk(a10);
        if (rB0 < NN) g_r[(size_t)rB0 * 32 + c2] = f.x;
        if (rB1 < NN) g_r[(size_t)rB1 * 32 + c2] = f.y;
        f = upk(a11v);
        if (rB0 < NN) g_r[(size_t)rB0 * 32 + 16 + c2] = f.x;
        if (rB1 < NN) g_r[(size_t)rB1 * 32 + 16 + c2] = f.y;
    }
}

// ---------------- layer-2 edge aggregation (flat, 4 threads/edge — champion form) ----------------
__global__ void k_agg_p(const int* __restrict__ ei32,
                        const long long* __restrict__ ei64) {
    int gid = blockIdx.x * blockDim.x + threadIdx.x;
    if (gid >= NE * 4) return;
    int e = gid >> 2;
    int c = gid & 3;
    int src, dst;
    if (g_is64) { src = (int)ei64[e]; dst = (int)ei64[NE + e]; }
    else        { src = ei32[e];      dst = ei32[NE + e]; }

    const float4 v = ((const float4*)(g_r + (size_t)src * 32))[c];
    red4(g_small + OFF_AGG2 + (size_t)dst * DOUT + 4 * c, v);
}

// ---------------- epilogue: softmax(agg2/deg + b2 + q) ----------------
__global__ void k_finalize(const float* __restrict__ b2,
                           float* __restrict__ out) {
    int row = blockIdx.x * blockDim.x + threadIdx.x;
    if (row >= NN) return;
    float inv = 1.0f / fmaxf(g_small[OFF_DEG + row], 1.0f);

    float v[DOUT];
    float mx = -1e30f;
#pragma unroll
    for (int j = 0; j < DOUT; j++) {
        v[j] = g_small[OFF_AGG2 + (size_t)row * DOUT + j] * inv + b2[j]
             + g_r[(size_t)row * 32 + 16 + j];
        mx = fmaxf(mx, v[j]);
    }
    float s = 0.f;
#pragma unroll
    for (int j = 0; j < DOUT; j++) {
        v[j] = __expf(v[j] - mx);
        s += v[j];
    }
    float is = 1.0f / s;
#pragma unroll
    for (int j = 0; j < DOUT; j++)
        out[(size_t)row * DOUT + j] = v[j] * is;
}

// ---------------- launch ----------------
extern "C" void kernel_launch(void* const* d_in, const int* in_sizes, int n_in,
                              void* d_out, int out_size) {
    const float*     x    = (const float*)d_in[0];
    const int*       ei32 = (const int*)d_in[1];
    const long long* ei64 = (const long long*)d_in[1];
    const float*     W1l  = (const float*)d_in[2];
    const float*     b1   = (const float*)d_in[3];
    const float*     W1r  = (const float*)d_in[4];
    const float*     W2l  = (const float*)d_in[5];
    const float*     b2   = (const float*)d_in[6];
    const float*     W2r  = (const float*)d_in[7];
    float* out = (float*)d_out;

    static cudaStream_t s1 = nullptr;
    static cudaEvent_t  evFork = nullptr, evJoin = nullptr;
    if (!s1) {
        cudaStreamCreateWithFlags(&s1, cudaStreamNonBlocking);
        cudaEventCreateWithFlags(&evFork, cudaEventDisableTiming);
        cudaEventCreateWithFlags(&evJoin, cudaEventDisableTiming);
    }

    void *smallp, *agg1p;
    cudaGetSymbolAddress(&smallp, g_small);
    cudaGetSymbolAddress(&agg1p,  g_agg1);

    // small zero (deg+agg2, 3.4 MB) + detect, then the big aggregation.
    // g_agg1 is already zero: statically on call 0, re-zeroed at end of every call.
    cudaMemsetAsync(smallp, 0, sizeof(float) * SMALL_TOTAL, 0);
    k_detect<<<1, 32>>>(ei32);
    k_agg_x <<<NE / EPB1, 256>>>(ei32, ei64, x);
    k_fused <<<(NN + RB - 1) / RB, 256>>>(x, W1l, b1, W1r, W2l, W2r);

    // fork: re-zero g_agg1 for the NEXT call, overlapped with agg_p + finalize
    cudaEventRecord(evFork, 0);
    cudaStreamWaitEvent(s1, evFork, 0);
    cudaMemsetAsync(agg1p, 0, sizeof(float) * NN * DIN, s1);
    cudaEventRecord(evJoin, s1);

    k_agg_p   <<<(NE * 4 + 255) / 256, 256>>>(ei32, ei64);
    k_finalize<<<(NN + 127) / 128, 128>>>(b2, out);

    // join: launch must not complete before the re-zero does
    cudaStreamWaitEvent(0, evJoin, 0);
}

// round 16
// speedup vs baseline: 1.2726x; 1.0240x over previous
#include <cuda_runtime.h>
#include <cstdint>

#define NN   50000
#define NE   800000
#define DIN  96
#define DH   128
#define DOUT 16
#define RB   64          // rows per fused block
#define EPB1 64          // edges per block, layer-1 agg

typedef unsigned long long ull;

// ---------------- scratch ----------------
// g_agg1: zeroed at END of each launch (overlapped); statically zero for call 0.
__device__ __align__(16) float g_agg1[NN * DIN];
// g_small: [deg | agg2], zeroed at start (3.4 MB, ~1 us)
#define OFF_DEG  0
#define OFF_AGG2 NN
#define SMALL_TOTAL (NN + NN * DOUT)
__device__ __align__(16) float g_small[SMALL_TOTAL];
__device__ __align__(16) float g_r[NN * 32];     // [p | q] = h @ [W2_l | W2_r]
__device__ int g_is64;

// ---------------- f32x2 packed helpers (sm_100+) ----------------
__device__ __forceinline__ ull pk(float a, float b) {
    ull r; asm("mov.b64 %0, {%1,%2};" : "=l"(r) : "f"(a), "f"(b)); return r;
}
__device__ __forceinline__ float2 upk(ull a) {
    float2 f; asm("mov.b64 {%0,%1}, %2;" : "=f"(f.x), "=f"(f.y) : "l"(a)); return f;
}
__device__ __forceinline__ ull fma2(ull a, ull b, ull c) {
    ull d; asm("fma.rn.f32x2 %0, %1, %2, %3;" : "=l"(d) : "l"(a), "l"(b), "l"(c)); return d;
}
__device__ __forceinline__ ull relu2(ull a) {
    float2 f = upk(a);
    return pk(fmaxf(f.x, 0.0f), fmaxf(f.y, 0.0f));
}
__device__ __forceinline__ void red4(float* g, float4 v) {
    asm volatile("red.global.add.v4.f32 [%0], {%1,%2,%3,%4};"
                 :: "l"(g), "f"(v.x), "f"(v.y), "f"(v.z), "f"(v.w) : "memory");
}

// ---------------- dtype detection (parallel) ----------------
__global__ void k_detect(const int* __restrict__ ei) {
    int lane = threadIdx.x;                  // 32 threads
    int ok = (ei[2 * lane + 1] == 0) && (ei[2 * lane + 65] == 0)
          && (ei[2 * lane + 129] == 0) && (ei[2 * lane + 193] == 0);
    unsigned all = __all_sync(0xffffffffu, ok);
    if (lane == 0) g_is64 = all ? 1 : 0;
}

// ---------------- layer-1 edge aggregation + degree (smem-staged indices) ----------------
// 64 edges per block; 256 threads x 6 iterations cover 64 edges x 24 float4 chunks.
__global__ void __launch_bounds__(256) k_agg_x(const int* __restrict__ ei32,
                                               const long long* __restrict__ ei64,
                                               const float* __restrict__ x) {
    __shared__ int ss[EPB1], sd[EPB1];
    const int tid = threadIdx.x;
    const int e0  = blockIdx.x * EPB1;

    if (tid < EPB1) {
        int e = e0 + tid;
        int s, d;
        if (g_is64) { s = (int)ei64[e]; d = (int)ei64[NE + e]; }
        else        { s = ei32[e];      d = ei32[NE + e]; }
        ss[tid] = s;
        sd[tid] = d;
        atomicAdd(&g_small[OFF_DEG + d], 1.0f);
    }
    __syncthreads();

#pragma unroll
    for (int i = 0; i < 6; i++) {
        int idx = i * 256 + tid;           // 0..1535 = 64 edges x 24 chunks
        int e = idx / 24;
        int c = idx - e * 24;
        const float4 v = ((const float4*)(x + (size_t)ss[e] * DIN))[c];
        red4(g_agg1 + (size_t)sd[e] * DIN + 4 * c, v);
    }
}

// ---------------- fused GEMMs: 64 rows/block, register-tiled 8 rows x 4 cols ----------------
__global__ void __launch_bounds__(256) k_fused(
        const float* __restrict__ x,
        const float* __restrict__ W1l,
        const float* __restrict__ b1,
        const float* __restrict__ W1r,
        const float* __restrict__ W2l,
        const float* __restrict__ W2r) {

    __shared__ __align__(16) char sm[49152];
    float* aspF = reinterpret_cast<float*>(sm);                 // [96][64]
    float* xspF = aspF + 96 * 64;                               // [96][64]
    ull*   hsT  = reinterpret_cast<ull*>(sm);                   // [32][128]
    float* wsTk = reinterpret_cast<float*>(sm + 32768);         // [128][32]

    const int tid  = threadIdx.x;
    const int row0 = blockIdx.x * RB;

    // staging: thread t -> row r = t>>2, k-chunk (t&3)*24; swizzle ull2-chunks mod 16
    {
        int r  = tid >> 2;
        int k0 = (tid & 3) * 24;
        int gnode = row0 + r;
        int q = r >> 2, lane = r & 3;
        if (gnode < NN) {
            float iv = 1.0f / fmaxf(g_small[OFF_DEG + gnode], 1.0f);
            const float* pa = g_agg1 + (size_t)gnode * DIN + k0;
            const float* px = x + (size_t)gnode * DIN + k0;
#pragma unroll
            for (int i = 0; i < 24; i += 4) {
                float4 a4 = *(const float4*)(pa + i);
                float4 x4 = *(const float4*)(px + i);
#pragma unroll
                for (int kk = 0; kk < 4; kk++) {
                    int k = k0 + i + kk;
                    int pos = k * 64 + (((q + k) & 15) << 2) + lane;
                    aspF[pos] = ((const float*)&a4)[kk] * iv;
                    xspF[pos] = ((const float*)&x4)[kk];
                }
            }
        } else {
#pragma unroll
            for (int i = 0; i < 24; i++) {
                int k = k0 + i;
                int pos = k * 64 + (((q + k) & 15) << 2) + lane;
                aspF[pos] = 0.0f;
                xspF[pos] = 0.0f;
            }
        }
    }
    __syncthreads();

    // stage A: thread (rg = tid>>5, cg = tid&31): rows 8rg..8rg+7, cols 4cg..4cg+3
    const int cg = tid & 31;
    const int rg = tid >> 5;

    ull acc[4][4];
    {
        float4 b4 = *(const float4*)(b1 + 4 * cg);
#pragma unroll
        for (int c = 0; c < 4; c++) {
            float bv = ((const float*)&b4)[c];
            ull bp = pk(bv, bv);
#pragma unroll
            for (int p = 0; p < 4; p++) acc[p][c] = bp;
        }
    }

    const ulonglong2* aU2 = (const ulonglong2*)aspF;   // [96][16]
    const ulonglong2* xU2 = (const ulonglong2*)xspF;

#pragma unroll 2
    for (int k = 0; k < DIN; k++) {
        int q0 = (2 * rg + k) & 15;
        int q1 = (2 * rg + 1 + k) & 15;
        ulonglong2 a01 = aU2[k * 16 + q0];
        ulonglong2 a23 = aU2[k * 16 + q1];
        ulonglong2 x01 = xU2[k * 16 + q0];
        ulonglong2 x23 = xU2[k * 16 + q1];
        float4 wl4 = __ldg((const float4*)(W1l + k * DH + 4 * cg));
        float4 wr4 = __ldg((const float4*)(W1r + k * DH + 4 * cg));
#pragma unroll
        for (int c = 0; c < 4; c++) {
            float wlv = ((const float*)&wl4)[c];
            float wrv = ((const float*)&wr4)[c];
            ull wl2 = pk(wlv, wlv);
            ull wr2 = pk(wrv, wrv);
            acc[0][c] = fma2(a01.x, wl2, acc[0][c]);
            acc[0][c] = fma2(x01.x, wr2, acc[0][c]);
            acc[1][c] = fma2(a01.y, wl2, acc[1][c]);
            acc[1][c] = fma2(x01.y, wr2, acc[1][c]);
            acc[2][c] = fma2(a23.x, wl2, acc[2][c]);
            acc[2][c] = fma2(x23.x, wr2, acc[2][c]);
            acc[3][c] = fma2(a23.y, wl2, acc[3][c]);
            acc[3][c] = fma2(x23.y, wr2, acc[3][c]);
        }
    }
    __syncthreads();   // asp/xsp reads complete before phase-2 overwrite

    // relu + store h (packed pairs) + load W2 (k-major)
#pragma unroll
    for (int p = 0; p < 4; p++) {
        ulonglong2* dstp = (ulonglong2*)(hsT + (size_t)(4 * rg + p) * DH + 4 * cg);
        ulonglong2 v0, v1;
        v0.x = relu2(acc[p][0]); v0.y = relu2(acc[p][1]);
        v1.x = relu2(acc[p][2]); v1.y = relu2(acc[p][3]);
        dstp[0] = v0; dstp[1] = v1;
    }
    for (int i = tid; i < DH * DOUT; i += 256) {
        int k = i >> 4, j = i & 15;
        wsTk[k * 32 + j]      = W2l[i];
        wsTk[k * 32 + 16 + j] = W2r[i];
    }
    __syncthreads();

    // stage B: thread (pg = tid>>4, c2 = tid&15): pairs {pg, pg+16}, cols {c2, c2+16}
    const int c2 = tid & 15;
    const int pg = tid >> 4;
    const ulonglong2* h0p = (const ulonglong2*)(hsT + (size_t)pg * DH);
    const ulonglong2* h1p = (const ulonglong2*)(hsT + (size_t)(pg + 16) * DH);

    ull a00 = 0, a01v = 0, a10 = 0, a11v = 0;
#pragma unroll 4
    for (int k4 = 0; k4 < DH / 4; k4++) {
        ulonglong2 hA0 = h0p[2 * k4], hA1 = h0p[2 * k4 + 1];
        ulonglong2 hB0 = h1p[2 * k4], hB1 = h1p[2 * k4 + 1];
#pragma unroll
        for (int kk = 0; kk < 4; kk++) {
            int k = 4 * k4 + kk;
            float w0 = wsTk[k * 32 + c2];
            float w1 = wsTk[k * 32 + 16 + c2];
            ull w0p = pk(w0, w0), w1p = pk(w1, w1);
            ull hA = (kk == 0) ? hA0.x : (kk == 1) ? hA0.y : (kk == 2) ? hA1.x : hA1.y;
            ull hB = (kk == 0) ? hB0.x : (kk == 1) ? hB0.y : (kk == 2) ? hB1.x : hB1.y;
            a00  = fma2(hA, w0p, a00);
            a01v = fma2(hA, w1p, a01v);
            a10  = fma2(hB, w0p, a10);
            a11v = fma2(hB, w1p, a11v);
        }
    }

    {
        int rA0 = row0 + 2 * pg,        rA1 = rA0 + 1;
        int rB0 = row0 + 2 * (pg + 16), rB1 = rB0 + 1;
        float2 f;
        f = upk(a00);
        if (rA0 < NN) g_r[(size_t)rA0 * 32 + c2] = f.x;
        if (rA1 < NN) g_r[(size_t)rA1 * 32 + c2] = f.y;
        f = upk(a01v);
        if (rA0 < NN) g_r[(size_t)rA0 * 32 + 16 + c2] = f.x;
        if (rA1 < NN) g_r[(size_t)rA1 * 32 + 16 + c2] = f.y;
        f = upk(a10);
        if (rB0 < NN) g_r[(size_t)rB0 * 32 + c2] = f.x;
        if (rB1 < NN) g_r[(size_t)rB1 * 32 + c2] = f.y;
        f = upk(a11v);
        if (rB0 < NN) g_r[(size_t)rB0 * 32 + 16 + c2] = f.x;
        if (rB1 < NN) g_r[(size_t)rB1 * 32 + 16 + c2] = f.y;
    }
}

// ---------------- layer-2 edge aggregation (flat, 4 threads/edge — champion form) ----------------
__global__ void k_agg_p(const int* __restrict__ ei32,
                        const long long* __restrict__ ei64) {
    int gid = blockIdx.x * blockDim.x + threadIdx.x;
    if (gid >= NE * 4) return;
    int e = gid >> 2;
    int c = gid & 3;
    int src, dst;
    if (g_is64) { src = (int)ei64[e]; dst = (int)ei64[NE + e]; }
    else        { src = ei32[e];      dst = ei32[NE + e]; }

    const float4 v = ((const float4*)(g_r + (size_t)src * 32))[c];
    red4(g_small + OFF_AGG2 + (size_t)dst * DOUT + 4 * c, v);
}

// ---------------- epilogue: softmax(agg2/deg + b2 + q), 4 threads per row ----------------
// thread = (row, quad c4): handles cols 4*c4..4*c4+3 via float4 loads; width-4 shuffles.
__global__ void __launch_bounds__(256) k_finalize(const float* __restrict__ b2,
                                                  float* __restrict__ out) {
    int gid = blockIdx.x * blockDim.x + threadIdx.x;
    int row = gid >> 2;
    int c4  = gid & 3;
    if (row >= NN) return;

    float inv = 1.0f / fmaxf(g_small[OFF_DEG + row], 1.0f);
    float4 a = *(const float4*)(g_small + OFF_AGG2 + (size_t)row * DOUT + 4 * c4);
    float4 q = *(const float4*)(g_r + (size_t)row * 32 + 16 + 4 * c4);
    float4 b = *(const float4*)(b2 + 4 * c4);

    float v0 = a.x * inv + b.x + q.x;
    float v1 = a.y * inv + b.y + q.y;
    float v2 = a.z * inv + b.z + q.z;
    float v3 = a.w * inv + b.w + q.w;

    // width-4 softmax across the quad lanes
    float mx = fmaxf(fmaxf(v0, v1), fmaxf(v2, v3));
    mx = fmaxf(mx, __shfl_xor_sync(0xffffffffu, mx, 1, 4));
    mx = fmaxf(mx, __shfl_xor_sync(0xffffffffu, mx, 2, 4));

    float e0 = __expf(v0 - mx), e1 = __expf(v1 - mx);
    float e2 = __expf(v2 - mx), e3 = __expf(v3 - mx);
    float s = e0 + e1 + e2 + e3;
    s += __shfl_xor_sync(0xffffffffu, s, 1, 4);
    s += __shfl_xor_sync(0xffffffffu, s, 2, 4);

    float is = 1.0f / s;
    *(float4*)(out + (size_t)row * DOUT + 4 * c4) =
        make_float4(e0 * is, e1 * is, e2 * is, e3 * is);
}

// ---------------- launch ----------------
extern "C" void kernel_launch(void* const* d_in, const int* in_sizes, int n_in,
                              void* d_out, int out_size) {
    const float*     x    = (const float*)d_in[0];
    const int*       ei32 = (const int*)d_in[1];
    const long long* ei64 = (const long long*)d_in[1];
    const float*     W1l  = (const float*)d_in[2];
    const float*     b1   = (const float*)d_in[3];
    const float*     W1r  = (const float*)d_in[4];
    const float*     W2l  = (const float*)d_in[5];
    const float*     b2   = (const float*)d_in[6];
    const float*     W2r  = (const float*)d_in[7];
    float* out = (float*)d_out;

    static cudaStream_t s1 = nullptr;
    static cudaEvent_t  evFork = nullptr, evJoin = nullptr;
    static cudaEvent_t  evFork2 = nullptr, evJoin2 = nullptr;
    if (!s1) {
        cudaStreamCreateWithFlags(&s1, cudaStreamNonBlocking);
        cudaEventCreateWithFlags(&evFork, cudaEventDisableTiming);
        cudaEventCreateWithFlags(&evJoin, cudaEventDisableTiming);
        cudaEventCreateWithFlags(&evFork2, cudaEventDisableTiming);
        cudaEventCreateWithFlags(&evJoin2, cudaEventDisableTiming);
    }

    void *smallp, *agg1p;
    cudaGetSymbolAddress(&smallp, g_small);
    cudaGetSymbolAddress(&agg1p,  g_agg1);

    // fork 1: dtype detect on side stream, concurrent with the small memset
    cudaEventRecord(evFork2, 0);
    cudaStreamWaitEvent(s1, evFork2, 0);
    k_detect<<<1, 32, 0, s1>>>(ei32);
    cudaEventRecord(evJoin2, s1);

    // main: small zero (deg+agg2, 3.4 MB); g_agg1 already zero (re-zeroed at tail).
    cudaMemsetAsync(smallp, 0, sizeof(float) * SMALL_TOTAL, 0);
    cudaStreamWaitEvent(0, evJoin2, 0);

    k_agg_x <<<NE / EPB1, 256>>>(ei32, ei64, x);
    k_fused <<<(NN + RB - 1) / RB, 256>>>(x, W1l, b1, W1r, W2l, W2r);

    // fork 2: re-zero g_agg1 for the NEXT call, overlapped with agg_p + finalize
    cudaEventRecord(evFork, 0);
    cudaStreamWaitEvent(s1, evFork, 0);
    cudaMemsetAsync(agg1p, 0, sizeof(float) * NN * DIN, s1);
    cudaEventRecord(evJoin, s1);

    k_agg_p   <<<(NE * 4 + 255) / 256, 256>>>(ei32, ei64);
    k_finalize<<<(NN * 4 + 255) / 256, 256>>>(b2, out);

    // join: launch must not complete before the re-zero does
    cudaStreamWaitEvent(0, evJoin, 0);
}

// round 17
// speedup vs baseline: 1.2729x; 1.0002x over previous
#include <cuda_runtime.h>
#include <cstdint>

#define NN   50000
#define NE   800000
#define DIN  96
#define DH   128
#define DOUT 16
#define RB   64          // rows per fused block
#define EPB1 64          // edges per block, layer-1 agg

typedef unsigned long long ull;

// ---------------- scratch ----------------
// g_agg1: zeroed at END of each launch (overlapped); statically zero for call 0.
__device__ __align__(16) float g_agg1[NN * DIN];
// g_small: [deg | agg2]. deg zeroed at start (200 KB); agg2 zeroed on side stream.
#define OFF_DEG  0
#define OFF_AGG2 NN
#define SMALL_TOTAL (NN + NN * DOUT)
__device__ __align__(16) float g_small[SMALL_TOTAL];
__device__ __align__(16) float g_r[NN * 32];     // [p | q] = h @ [W2_l | W2_r]
__device__ int g_is64;

// ---------------- f32x2 packed helpers (sm_100+) ----------------
__device__ __forceinline__ ull pk(float a, float b) {
    ull r; asm("mov.b64 %0, {%1,%2};" : "=l"(r) : "f"(a), "f"(b)); return r;
}
__device__ __forceinline__ float2 upk(ull a) {
    float2 f; asm("mov.b64 {%0,%1}, %2;" : "=f"(f.x), "=f"(f.y) : "l"(a)); return f;
}
__device__ __forceinline__ ull fma2(ull a, ull b, ull c) {
    ull d; asm("fma.rn.f32x2 %0, %1, %2, %3;" : "=l"(d) : "l"(a), "l"(b), "l"(c)); return d;
}
__device__ __forceinline__ ull relu2(ull a) {
    float2 f = upk(a);
    return pk(fmaxf(f.x, 0.0f), fmaxf(f.y, 0.0f));
}
__device__ __forceinline__ void red4(float* g, float4 v) {
    asm volatile("red.global.add.v4.f32 [%0], {%1,%2,%3,%4};"
                 :: "l"(g), "f"(v.x), "f"(v.y), "f"(v.z), "f"(v.w) : "memory");
}

// ---------------- dtype detection (parallel) ----------------
__global__ void k_detect(const int* __restrict__ ei) {
    int lane = threadIdx.x;                  // 32 threads
    int ok = (ei[2 * lane + 1] == 0) && (ei[2 * lane + 65] == 0)
          && (ei[2 * lane + 129] == 0) && (ei[2 * lane + 193] == 0);
    unsigned all = __all_sync(0xffffffffu, ok);
    if (lane == 0) g_is64 = all ? 1 : 0;
}

// ---------------- layer-1 edge aggregation + degree (smem-staged indices) ----------------
// 64 edges per block; 256 threads x 6 iterations cover 64 edges x 24 float4 chunks.
__global__ void __launch_bounds__(256) k_agg_x(const int* __restrict__ ei32,
                                               const long long* __restrict__ ei64,
                                               const float* __restrict__ x) {
    __shared__ int ss[EPB1], sd[EPB1];
    const int tid = threadIdx.x;
    const int e0  = blockIdx.x * EPB1;

    if (tid < EPB1) {
        int e = e0 + tid;
        int s, d;
        if (g_is64) { s = (int)ei64[e]; d = (int)ei64[NE + e]; }
        else        { s = ei32[e];      d = ei32[NE + e]; }
        ss[tid] = s;
        sd[tid] = d;
        atomicAdd(&g_small[OFF_DEG + d], 1.0f);
    }
    __syncthreads();

#pragma unroll
    for (int i = 0; i < 6; i++) {
        int idx = i * 256 + tid;           // 0..1535 = 64 edges x 24 chunks
        int e = idx / 24;
        int c = idx - e * 24;
        const float4 v = ((const float4*)(x + (size_t)ss[e] * DIN))[c];
        red4(g_agg1 + (size_t)sd[e] * DIN + 4 * c, v);
    }
}

// ---------------- fused GEMMs: 64 rows/block, register-tiled 8 rows x 4 cols ----------------
__global__ void __launch_bounds__(256) k_fused(
        const float* __restrict__ x,
        const float* __restrict__ W1l,
        const float* __restrict__ b1,
        const float* __restrict__ W1r,
        const float* __restrict__ W2l,
        const float* __restrict__ W2r) {

    __shared__ __align__(16) char sm[49152];
    float* aspF = reinterpret_cast<float*>(sm);                 // [96][64]
    float* xspF = aspF + 96 * 64;                               // [96][64]
    ull*   hsT  = reinterpret_cast<ull*>(sm);                   // [32][128]
    float* wsTk = reinterpret_cast<float*>(sm + 32768);         // [128][32]

    const int tid  = threadIdx.x;
    const int row0 = blockIdx.x * RB;

    // staging: thread t -> row r = t>>2, k-chunk (t&3)*24; swizzle ull2-chunks mod 16
    {
        int r  = tid >> 2;
        int k0 = (tid & 3) * 24;
        int gnode = row0 + r;
        int q = r >> 2, lane = r & 3;
        if (gnode < NN) {
            float iv = 1.0f / fmaxf(g_small[OFF_DEG + gnode], 1.0f);
            const float* pa = g_agg1 + (size_t)gnode * DIN + k0;
            const float* px = x + (size_t)gnode * DIN + k0;
#pragma unroll
            for (int i = 0; i < 24; i += 4) {
                float4 a4 = *(const float4*)(pa + i);
                float4 x4 = *(const float4*)(px + i);
#pragma unroll
                for (int kk = 0; kk < 4; kk++) {
                    int k = k0 + i + kk;
                    int pos = k * 64 + (((q + k) & 15) << 2) + lane;
                    aspF[pos] = ((const float*)&a4)[kk] * iv;
                    xspF[pos] = ((const float*)&x4)[kk];
                }
            }
        } else {
#pragma unroll
            for (int i = 0; i < 24; i++) {
                int k = k0 + i;
                int pos = k * 64 + (((q + k) & 15) << 2) + lane;
                aspF[pos] = 0.0f;
                xspF[pos] = 0.0f;
            }
        }
    }
    __syncthreads();

    // stage A: thread (rg = tid>>5, cg = tid&31): rows 8rg..8rg+7, cols 4cg..4cg+3
    const int cg = tid & 31;
    const int rg = tid >> 5;

    ull acc[4][4];
    {
        float4 b4 = *(const float4*)(b1 + 4 * cg);
#pragma unroll
        for (int c = 0; c < 4; c++) {
            float bv = ((const float*)&b4)[c];
            ull bp = pk(bv, bv);
#pragma unroll
            for (int p = 0; p < 4; p++) acc[p][c] = bp;
        }
    }

    const ulonglong2* aU2 = (const ulonglong2*)aspF;   // [96][16]
    const ulonglong2* xU2 = (const ulonglong2*)xspF;

#pragma unroll 2
    for (int k = 0; k < DIN; k++) {
        int q0 = (2 * rg + k) & 15;
        int q1 = (2 * rg + 1 + k) & 15;
        ulonglong2 a01 = aU2[k * 16 + q0];
        ulonglong2 a23 = aU2[k * 16 + q1];
        ulonglong2 x01 = xU2[k * 16 + q0];
        ulonglong2 x23 = xU2[k * 16 + q1];
        float4 wl4 = __ldg((const float4*)(W1l + k * DH + 4 * cg));
        float4 wr4 = __ldg((const float4*)(W1r + k * DH + 4 * cg));
#pragma unroll
        for (int c = 0; c < 4; c++) {
            float wlv = ((const float*)&wl4)[c];
            float wrv = ((const float*)&wr4)[c];
            ull wl2 = pk(wlv, wlv);
            ull wr2 = pk(wrv, wrv);
            acc[0][c] = fma2(a01.x, wl2, acc[0][c]);
            acc[0][c] = fma2(x01.x, wr2, acc[0][c]);
            acc[1][c] = fma2(a01.y, wl2, acc[1][c]);
            acc[1][c] = fma2(x01.y, wr2, acc[1][c]);
            acc[2][c] = fma2(a23.x, wl2, acc[2][c]);
            acc[2][c] = fma2(x23.x, wr2, acc[2][c]);
            acc[3][c] = fma2(a23.y, wl2, acc[3][c]);
            acc[3][c] = fma2(x23.y, wr2, acc[3][c]);
        }
    }
    __syncthreads();   // asp/xsp reads complete before phase-2 overwrite

    // relu + store h (packed pairs) + load W2 (k-major)
#pragma unroll
    for (int p = 0; p < 4; p++) {
        ulonglong2* dstp = (ulonglong2*)(hsT + (size_t)(4 * rg + p) * DH + 4 * cg);
        ulonglong2 v0, v1;
        v0.x = relu2(acc[p][0]); v0.y = relu2(acc[p][1]);
        v1.x = relu2(acc[p][2]); v1.y = relu2(acc[p][3]);
        dstp[0] = v0; dstp[1] = v1;
    }
    for (int i = tid; i < DH * DOUT; i += 256) {
        int k = i >> 4, j = i & 15;
        wsTk[k * 32 + j]      = W2l[i];
        wsTk[k * 32 + 16 + j] = W2r[i];
    }
    __syncthreads();

    // stage B: thread (pg = tid>>4, c1 = tid&15): pairs {pg, pg+16}, col-pair {2c1, 2c1+1}
    // adjacent columns -> LDS.64 weight loads and STG.64 result stores
    const int c1 = tid & 15;
    const int pg = tid >> 4;
    const ulonglong2* h0p = (const ulonglong2*)(hsT + (size_t)pg * DH);
    const ulonglong2* h1p = (const ulonglong2*)(hsT + (size_t)(pg + 16) * DH);

    ull a00 = 0, a01v = 0, a10 = 0, a11v = 0;   // (pairA,col0) (pairA,col1) (pairB,col0) (pairB,col1)
#pragma unroll 4
    for (int k4 = 0; k4 < DH / 4; k4++) {
        ulonglong2 hA0 = h0p[2 * k4], hA1 = h0p[2 * k4 + 1];
        ulonglong2 hB0 = h1p[2 * k4], hB1 = h1p[2 * k4 + 1];
#pragma unroll
        for (int kk = 0; kk < 4; kk++) {
            int k = 4 * k4 + kk;
            float2 w2 = *(const float2*)(wsTk + k * 32 + 2 * c1);   // LDS.64
            ull w0p = pk(w2.x, w2.x), w1p = pk(w2.y, w2.y);
            ull hA = (kk == 0) ? hA0.x : (kk == 1) ? hA0.y : (kk == 2) ? hA1.x : hA1.y;
            ull hB = (kk == 0) ? hB0.x : (kk == 1) ? hB0.y : (kk == 2) ? hB1.x : hB1.y;
            a00  = fma2(hA, w0p, a00);
            a01v = fma2(hA, w1p, a01v);
            a10  = fma2(hB, w0p, a10);
            a11v = fma2(hB, w1p, a11v);
        }
    }

    {
        int rA0 = row0 + 2 * pg,        rA1 = rA0 + 1;
        int rB0 = row0 + 2 * (pg + 16), rB1 = rB0 + 1;
        float2 fA0 = upk(a00), fA1 = upk(a01v);    // (col0 rowA0/rowA1), (col1 rowA0/rowA1)
        float2 fB0 = upk(a10), fB1 = upk(a11v);
        if (rA0 < NN) *(float2*)(g_r + (size_t)rA0 * 32 + 2 * c1) = make_float2(fA0.x, fA1.x);
        if (rA1 < NN) *(float2*)(g_r + (size_t)rA1 * 32 + 2 * c1) = make_float2(fA0.y, fA1.y);
        if (rB0 < NN) *(float2*)(g_r + (size_t)rB0 * 32 + 2 * c1) = make_float2(fB0.x, fB1.x);
        if (rB1 < NN) *(float2*)(g_r + (size_t)rB1 * 32 + 2 * c1) = make_float2(fB0.y, fB1.y);
    }
}

// ---------------- layer-2 edge aggregation (flat, 4 threads/edge — champion form) ----------------
__global__ void k_agg_p(const int* __restrict__ ei32,
                        const long long* __restrict__ ei64) {
    int gid = blockIdx.x * blockDim.x + threadIdx.x;
    if (gid >= NE * 4) return;
    int e = gid >> 2;
    int c = gid & 3;
    int src, dst;
    if (g_is64) { src = (int)ei64[e]; dst = (int)ei64[NE + e]; }
    else        { src = ei32[e];      dst = ei32[NE + e]; }

    const float4 v = ((const float4*)(g_r + (size_t)src * 32))[c];
    red4(g_small + OFF_AGG2 + (size_t)dst * DOUT + 4 * c, v);
}

// ---------------- epilogue: softmax(agg2/deg + b2 + q), 4 threads per row ----------------
__global__ void __launch_bounds__(128) k_finalize(const float* __restrict__ b2,
                                                  float* __restrict__ out) {
    int gid = blockIdx.x * blockDim.x + threadIdx.x;
    int row = gid >> 2;
    int c4  = gid & 3;
    if (row >= NN) return;

    float inv = 1.0f / fmaxf(g_small[OFF_DEG + row], 1.0f);
    float4 a = *(const float4*)(g_small + OFF_AGG2 + (size_t)row * DOUT + 4 * c4);
    float4 q = *(const float4*)(g_r + (size_t)row * 32 + 16 + 4 * c4);
    float4 b = *(const float4*)(b2 + 4 * c4);

    float v0 = a.x * inv + b.x + q.x;
    float v1 = a.y * inv + b.y + q.y;
    float v2 = a.z * inv + b.z + q.z;
    float v3 = a.w * inv + b.w + q.w;

    // width-4 softmax across the quad lanes
    float mx = fmaxf(fmaxf(v0, v1), fmaxf(v2, v3));
    mx = fmaxf(mx, __shfl_xor_sync(0xffffffffu, mx, 1, 4));
    mx = fmaxf(mx, __shfl_xor_sync(0xffffffffu, mx, 2, 4));

    float e0 = __expf(v0 - mx), e1 = __expf(v1 - mx);
    float e2 = __expf(v2 - mx), e3 = __expf(v3 - mx);
    float s = e0 + e1 + e2 + e3;
    s += __shfl_xor_sync(0xffffffffu, s, 1, 4);
    s += __shfl_xor_sync(0xffffffffu, s, 2, 4);

    float is = 1.0f / s;
    *(float4*)(out + (size_t)row * DOUT + 4 * c4) =
        make_float4(e0 * is, e1 * is, e2 * is, e3 * is);
}

// ---------------- launch ----------------
extern "C" void kernel_launch(void* const* d_in, const int* in_sizes, int n_in,
                              void* d_out, int out_size) {
    const float*     x    = (const float*)d_in[0];
    const int*       ei32 = (const int*)d_in[1];
    const long long* ei64 = (const long long*)d_in[1];
    const float*     W1l  = (const float*)d_in[2];
    const float*     b1   = (const float*)d_in[3];
    const float*     W1r  = (const float*)d_in[4];
    const float*     W2l  = (const float*)d_in[5];
    const float*     b2   = (const float*)d_in[6];
    const float*     W2r  = (const float*)d_in[7];
    float* out = (float*)d_out;

    static cudaStream_t s1 = nullptr;
    static cudaEvent_t  evFork = nullptr, evJoin = nullptr;
    static cudaEvent_t  evFork2 = nullptr, evJoin2 = nullptr;
    if (!s1) {
        cudaStreamCreateWithFlags(&s1, cudaStreamNonBlocking);
        cudaEventCreateWithFlags(&evFork, cudaEventDisableTiming);
        cudaEventCreateWithFlags(&evJoin, cudaEventDisableTiming);
        cudaEventCreateWithFlags(&evFork2, cudaEventDisableTiming);
        cudaEventCreateWithFlags(&evJoin2, cudaEventDisableTiming);
    }

    void *smallp, *agg1p;
    cudaGetSymbolAddress(&smallp, g_small);
    cudaGetSymbolAddress(&agg1p,  g_agg1);

    // fork 1: dtype detect + agg2 zero on side stream (agg2 not needed until k_agg_p)
    cudaEventRecord(evFork2, 0);
    cudaStreamWaitEvent(s1, evFork2, 0);
    k_detect<<<1, 32, 0, s1>>>(ei32);
    cudaMemsetAsync((char*)smallp + sizeof(float) * OFF_AGG2, 0,
                    sizeof(float) * NN * DOUT, s1);
    cudaEventRecord(evJoin2, s1);

    // main: deg zero only (200 KB); g_agg1 already zero (re-zeroed at tail).
    cudaMemsetAsync(smallp, 0, sizeof(float) * NN, 0);
    // agg_x needs detect result — s1's detect finishes well within the memset;
    // wait on evJoin2 to be safe (also orders the agg2 zero before agg_p below).
    cudaStreamWaitEvent(0, evJoin2, 0);

    k_agg_x <<<NE / EPB1, 256>>>(ei32, ei64, x);
    k_fused <<<(NN + RB - 1) / RB, 256>>>(x, W1l, b1, W1r, W2l, W2r);

    // fork 2: re-zero g_agg1 for the NEXT call, overlapped with agg_p + finalize
    cudaEventRecord(evFork, 0);
    cudaStreamWaitEvent(s1, evFork, 0);
    cudaMemsetAsync(agg1p, 0, sizeof(float) * NN * DIN, s1);
    cudaEventRecord(evJoin, s1);

    k_agg_p   <<<(NE * 4 + 255) / 256, 256>>>(ei32, ei64);
    k_finalize<<<(NN * 4 + 127) / 128, 128>>>(b2, out);

    // join: launch must not complete before the re-zero does
    cudaStreamWaitEvent(0, evJoin, 0);
}